// round 1
// baseline (speedup 1.0000x reference)
#include <cuda_runtime.h>
#include <cuda_bf16.h>

#define SEQ 2048
#define DIM 64
#define NBH 32   // B*H = 2*16

__inline__ __device__ float warpMax(float v) {
    #pragma unroll
    for (int o = 16; o > 0; o >>= 1) v = fmaxf(v, __shfl_xor_sync(0xffffffffu, v, o));
    return v;
}
__inline__ __device__ float warpSum(float v) {
    #pragma unroll
    for (int o = 16; o > 0; o >>= 1) v += __shfl_xor_sync(0xffffffffu, v, o);
    return v;
}

// Kernel 1: one block per (query row, bh). Computes scores = QK^T/8, masks,
// softmax over the row, writes the attn row.
__global__ __launch_bounds__(256) void scores_softmax_kernel(
    const float* __restrict__ Q,
    const float* __restrict__ K,
    const int*   __restrict__ mask,
    float*       __restrict__ attn)
{
    const int q  = blockIdx.x;   // 0..SEQ-1
    const int bh = blockIdx.y;   // 0..NBH-1
    const int tid = threadIdx.x;

    __shared__ float sc[SEQ];      // 8 KB
    __shared__ float qs[DIM];
    __shared__ float red[8];

    if (tid < DIM)
        qs[tid] = Q[(size_t)bh * SEQ * DIM + (size_t)q * DIM + tid];
    __syncthreads();

    const float scale = 0.125f;  // 1/sqrt(64)
    const float4* K4 = (const float4*)(K + (size_t)bh * SEQ * DIM);
    const int* mrow = mask + (size_t)q * SEQ;

    for (int j = tid; j < SEQ; j += 256) {
        const float4* kr = K4 + (size_t)j * (DIM / 4);
        float dot = 0.f;
        #pragma unroll
        for (int d4 = 0; d4 < DIM / 4; d4++) {
            float4 k = kr[d4];
            dot += qs[d4*4+0]*k.x + qs[d4*4+1]*k.y
                 + qs[d4*4+2]*k.z + qs[d4*4+3]*k.w;
        }
        dot *= scale;
        if (mrow[j] == 0) dot = -1.0e9f;
        sc[j] = dot;
    }
    __syncthreads();

    // row max
    float m = -3.0e38f;
    for (int j = tid; j < SEQ; j += 256) m = fmaxf(m, sc[j]);
    m = warpMax(m);
    if ((tid & 31) == 0) red[tid >> 5] = m;
    __syncthreads();
    if (tid < 32) {
        float v = (tid < 8) ? red[tid] : -3.0e38f;
        v = warpMax(v);
        if (tid == 0) red[0] = v;
    }
    __syncthreads();
    m = red[0];
    __syncthreads();

    // exp + sum
    float s = 0.f;
    for (int j = tid; j < SEQ; j += 256) {
        float e = __expf(sc[j] - m);
        sc[j] = e;
        s += e;
    }
    s = warpSum(s);
    if ((tid & 31) == 0) red[tid >> 5] = s;
    __syncthreads();
    if (tid < 32) {
        float v = (tid < 8) ? red[tid] : 0.f;
        v = warpSum(v);
        if (tid == 0) red[0] = v;
    }
    __syncthreads();
    const float inv = 1.0f / red[0];

    float* arow = attn + ((size_t)bh * SEQ + q) * SEQ;
    for (int j = tid; j < SEQ; j += 256) {
        arow[j] = sc[j] * inv;
    }
}

// Kernel 2: out = attn @ V.  M=SEQ, N=DIM(64), K=SEQ per bh.
// Block computes a 64x64 output tile (64 rows x full 64 cols).
// 256 threads as 16x16; each thread owns a 4x4 micro-tile.
__global__ __launch_bounds__(256) void attnv_kernel(
    const float* __restrict__ attn,
    const float* __restrict__ V,
    float*       __restrict__ out)
{
    const int bh = blockIdx.y;
    const int m0 = blockIdx.x * 64;
    const int tid = threadIdx.x;
    const int tx = tid & 15;   // col group
    const int ty = tid >> 4;   // row group

    __shared__ float As[64][64];   // attn tile (rows x k)
    __shared__ float Vs[64][64];   // V tile (k x cols)

    float acc[4][4] = {};

    const float* abase = attn + (size_t)bh * SEQ * SEQ;
    const float* vbase = V + (size_t)bh * SEQ * DIM;

    for (int kt = 0; kt < SEQ; kt += 64) {
        // load 64x64 attn tile (float4 per thread x 4)
        #pragma unroll
        for (int it = 0; it < 4; it++) {
            int i = tid + it * 256;      // 0..1023, each is one float4 slot
            int r = i >> 4;              // 0..63
            int c4 = i & 15;             // 0..15
            float4 v = *(const float4*)&abase[((size_t)(m0 + r)) * SEQ + kt + c4 * 4];
            *(float4*)&As[r][c4 * 4] = v;
        }
        // load 64x64 V tile
        #pragma unroll
        for (int it = 0; it < 4; it++) {
            int i = tid + it * 256;
            int r = i >> 4;
            int c4 = i & 15;
            float4 v = *(const float4*)&vbase[(size_t)(kt + r) * DIM + c4 * 4];
            *(float4*)&Vs[r][c4 * 4] = v;
        }
        __syncthreads();

        #pragma unroll
        for (int kk = 0; kk < 64; kk++) {
            float a0 = As[ty * 4 + 0][kk];
            float a1 = As[ty * 4 + 1][kk];
            float a2 = As[ty * 4 + 2][kk];
            float a3 = As[ty * 4 + 3][kk];
            float b0 = Vs[kk][tx * 4 + 0];
            float b1 = Vs[kk][tx * 4 + 1];
            float b2 = Vs[kk][tx * 4 + 2];
            float b3 = Vs[kk][tx * 4 + 3];
            acc[0][0] += a0 * b0; acc[0][1] += a0 * b1; acc[0][2] += a0 * b2; acc[0][3] += a0 * b3;
            acc[1][0] += a1 * b0; acc[1][1] += a1 * b1; acc[1][2] += a1 * b2; acc[1][3] += a1 * b3;
            acc[2][0] += a2 * b0; acc[2][1] += a2 * b1; acc[2][2] += a2 * b2; acc[2][3] += a2 * b3;
            acc[3][0] += a3 * b0; acc[3][1] += a3 * b1; acc[3][2] += a3 * b2; acc[3][3] += a3 * b3;
        }
        __syncthreads();
    }

    #pragma unroll
    for (int r = 0; r < 4; r++) {
        float4 v = make_float4(acc[r][0], acc[r][1], acc[r][2], acc[r][3]);
        *(float4*)&out[((size_t)bh * SEQ + m0 + ty * 4 + r) * DIM + tx * 4] = v;
    }
}

extern "C" void kernel_launch(void* const* d_in, const int* in_sizes, int n_in,
                              void* d_out, int out_size) {
    const float* Q    = (const float*)d_in[0];
    const float* K    = (const float*)d_in[1];
    const float* V    = (const float*)d_in[2];
    const int*   mask = (const int*)d_in[3];

    float* out  = (float*)d_out;                              // [B,H,S,D]
    float* attn = out + (size_t)NBH * SEQ * DIM;              // [B,H,S,S]

    dim3 g1(SEQ, NBH);
    scores_softmax_kernel<<<g1, 256>>>(Q, K, mask, attn);

    dim3 g2(SEQ / 64, NBH);
    attnv_kernel<<<g2, 256>>>(attn, V, out);
}

// round 2
// speedup vs baseline: 7.1339x; 7.1339x over previous
#include <cuda_runtime.h>
#include <cuda_bf16.h>

#define SEQ 2048
#define DIM 64
#define NBH 32   // B*H = 2*16

__inline__ __device__ float warpMax(float v) {
    #pragma unroll
    for (int o = 16; o > 0; o >>= 1) v = fmaxf(v, __shfl_xor_sync(0xffffffffu, v, o));
    return v;
}
__inline__ __device__ float warpSum(float v) {
    #pragma unroll
    for (int o = 16; o > 0; o >>= 1) v += __shfl_xor_sync(0xffffffffu, v, o);
    return v;
}

// Kernel 1: scores = (Q @ K^T) * 0.125    (NT GEMM, M=N=2048, K=64 per bh)
// 64x64 output tile per block, 256 threads, 4x4 micro-tile per thread.
__global__ __launch_bounds__(256) void qk_kernel(
    const float* __restrict__ Q,
    const float* __restrict__ K,
    float*       __restrict__ scores)
{
    const int bh = blockIdx.z;
    const int m0 = blockIdx.y * 64;
    const int n0 = blockIdx.x * 64;
    const int tid = threadIdx.x;

    __shared__ float Qs[64][64];   // [m][d]
    __shared__ float Ks[64][65];   // [n][d], padded to avoid 16-way conflicts

    const float4* Q4 = (const float4*)(Q + (size_t)bh * SEQ * DIM);
    const float4* K4 = (const float4*)(K + (size_t)bh * SEQ * DIM);

    #pragma unroll
    for (int p = 0; p < 4; p++) {
        int lin = p * 256 + tid;       // 0..1023
        int r  = lin >> 4;             // row 0..63
        int d4 = lin & 15;             // float4 col 0..15
        float4 v = Q4[(size_t)(m0 + r) * (DIM / 4) + d4];
        *(float4*)&Qs[r][d4 * 4] = v;
    }
    #pragma unroll
    for (int p = 0; p < 4; p++) {
        int lin = p * 256 + tid;
        int r  = lin >> 4;
        int d4 = lin & 15;
        float4 v = K4[(size_t)(n0 + r) * (DIM / 4) + d4];
        Ks[r][d4 * 4 + 0] = v.x;
        Ks[r][d4 * 4 + 1] = v.y;
        Ks[r][d4 * 4 + 2] = v.z;
        Ks[r][d4 * 4 + 3] = v.w;
    }
    __syncthreads();

    const int tx = tid & 15;   // n group
    const int ty = tid >> 4;   // m group
    float acc[4][4] = {};

    #pragma unroll 8
    for (int d = 0; d < 64; d++) {
        float a0 = Qs[ty * 4 + 0][d];
        float a1 = Qs[ty * 4 + 1][d];
        float a2 = Qs[ty * 4 + 2][d];
        float a3 = Qs[ty * 4 + 3][d];
        float b0 = Ks[tx * 4 + 0][d];
        float b1 = Ks[tx * 4 + 1][d];
        float b2 = Ks[tx * 4 + 2][d];
        float b3 = Ks[tx * 4 + 3][d];
        acc[0][0] += a0 * b0; acc[0][1] += a0 * b1; acc[0][2] += a0 * b2; acc[0][3] += a0 * b3;
        acc[1][0] += a1 * b0; acc[1][1] += a1 * b1; acc[1][2] += a1 * b2; acc[1][3] += a1 * b3;
        acc[2][0] += a2 * b0; acc[2][1] += a2 * b1; acc[2][2] += a2 * b2; acc[2][3] += a2 * b3;
        acc[3][0] += a3 * b0; acc[3][1] += a3 * b1; acc[3][2] += a3 * b2; acc[3][3] += a3 * b3;
    }

    const float scale = 0.125f;   // 1/sqrt(64)
    float* sbase = scores + (size_t)bh * SEQ * SEQ;
    #pragma unroll
    for (int r = 0; r < 4; r++) {
        float4 v = make_float4(acc[r][0] * scale, acc[r][1] * scale,
                               acc[r][2] * scale, acc[r][3] * scale);
        *(float4*)&sbase[(size_t)(m0 + ty * 4 + r) * SEQ + n0 + tx * 4] = v;
    }
}

// Kernel 2: in-place masked softmax over each row of scores -> attn.
// One block per (q, bh) row; 256 threads, 8 floats each, all in registers.
__global__ __launch_bounds__(256) void softmax_kernel(
    float*     __restrict__ attn,
    const int* __restrict__ mask)
{
    const int q  = blockIdx.x;
    const int bh = blockIdx.y;
    const int tid = threadIdx.x;

    float4* row = (float4*)(attn + ((size_t)bh * SEQ + q) * SEQ);
    const int4* mrow = (const int4*)(mask + (size_t)q * SEQ);

    __shared__ float red[8];

    float4 v0 = row[tid];
    float4 v1 = row[tid + 256];
    int4 k0 = mrow[tid];
    int4 k1 = mrow[tid + 256];

    v0.x = (k0.x == 0) ? -1.0e9f : v0.x;
    v0.y = (k0.y == 0) ? -1.0e9f : v0.y;
    v0.z = (k0.z == 0) ? -1.0e9f : v0.z;
    v0.w = (k0.w == 0) ? -1.0e9f : v0.w;
    v1.x = (k1.x == 0) ? -1.0e9f : v1.x;
    v1.y = (k1.y == 0) ? -1.0e9f : v1.y;
    v1.z = (k1.z == 0) ? -1.0e9f : v1.z;
    v1.w = (k1.w == 0) ? -1.0e9f : v1.w;

    float m = fmaxf(fmaxf(fmaxf(v0.x, v0.y), fmaxf(v0.z, v0.w)),
                    fmaxf(fmaxf(v1.x, v1.y), fmaxf(v1.z, v1.w)));
    m = warpMax(m);
    if ((tid & 31) == 0) red[tid >> 5] = m;
    __syncthreads();
    if (tid < 32) {
        float t = (tid < 8) ? red[tid] : -3.0e38f;
        t = warpMax(t);
        if (tid == 0) red[0] = t;
    }
    __syncthreads();
    m = red[0];
    __syncthreads();

    v0.x = __expf(v0.x - m); v0.y = __expf(v0.y - m);
    v0.z = __expf(v0.z - m); v0.w = __expf(v0.w - m);
    v1.x = __expf(v1.x - m); v1.y = __expf(v1.y - m);
    v1.z = __expf(v1.z - m); v1.w = __expf(v1.w - m);

    float s = (v0.x + v0.y) + (v0.z + v0.w) + (v1.x + v1.y) + (v1.z + v1.w);
    s = warpSum(s);
    if ((tid & 31) == 0) red[tid >> 5] = s;
    __syncthreads();
    if (tid < 32) {
        float t = (tid < 8) ? red[tid] : 0.f;
        t = warpSum(t);
        if (tid == 0) red[0] = t;
    }
    __syncthreads();
    const float inv = 1.0f / red[0];

    v0.x *= inv; v0.y *= inv; v0.z *= inv; v0.w *= inv;
    v1.x *= inv; v1.y *= inv; v1.z *= inv; v1.w *= inv;
    row[tid] = v0;
    row[tid + 256] = v1;
}

// Kernel 3: out = attn @ V.  (NN GEMM, M=SEQ, N=64, K=SEQ per bh)
__global__ __launch_bounds__(256) void attnv_kernel(
    const float* __restrict__ attn,
    const float* __restrict__ V,
    float*       __restrict__ out)
{
    const int bh = blockIdx.y;
    const int m0 = blockIdx.x * 64;
    const int tid = threadIdx.x;
    const int tx = tid & 15;
    const int ty = tid >> 4;

    __shared__ float As[64][64];   // attn tile [m][k]
    __shared__ float Vs[64][64];   // V tile [k][n]

    float acc[4][4] = {};

    const float* abase = attn + (size_t)bh * SEQ * SEQ;
    const float* vbase = V + (size_t)bh * SEQ * DIM;

    for (int kt = 0; kt < SEQ; kt += 64) {
        #pragma unroll
        for (int it = 0; it < 4; it++) {
            int i = tid + it * 256;
            int r = i >> 4;
            int c4 = i & 15;
            float4 v = *(const float4*)&abase[((size_t)(m0 + r)) * SEQ + kt + c4 * 4];
            *(float4*)&As[r][c4 * 4] = v;
        }
        #pragma unroll
        for (int it = 0; it < 4; it++) {
            int i = tid + it * 256;
            int r = i >> 4;
            int c4 = i & 15;
            float4 v = *(const float4*)&vbase[(size_t)(kt + r) * DIM + c4 * 4];
            *(float4*)&Vs[r][c4 * 4] = v;
        }
        __syncthreads();

        #pragma unroll 8
        for (int kk = 0; kk < 64; kk++) {
            float a0 = As[ty * 4 + 0][kk];
            float a1 = As[ty * 4 + 1][kk];
            float a2 = As[ty * 4 + 2][kk];
            float a3 = As[ty * 4 + 3][kk];
            float b0 = Vs[kk][tx * 4 + 0];
            float b1 = Vs[kk][tx * 4 + 1];
            float b2 = Vs[kk][tx * 4 + 2];
            float b3 = Vs[kk][tx * 4 + 3];
            acc[0][0] += a0 * b0; acc[0][1] += a0 * b1; acc[0][2] += a0 * b2; acc[0][3] += a0 * b3;
            acc[1][0] += a1 * b0; acc[1][1] += a1 * b1; acc[1][2] += a1 * b2; acc[1][3] += a1 * b3;
            acc[2][0] += a2 * b0; acc[2][1] += a2 * b1; acc[2][2] += a2 * b2; acc[2][3] += a2 * b3;
            acc[3][0] += a3 * b0; acc[3][1] += a3 * b1; acc[3][2] += a3 * b2; acc[3][3] += a3 * b3;
        }
        __syncthreads();
    }

    #pragma unroll
    for (int r = 0; r < 4; r++) {
        float4 v = make_float4(acc[r][0], acc[r][1], acc[r][2], acc[r][3]);
        *(float4*)&out[((size_t)bh * SEQ + m0 + ty * 4 + r) * DIM + tx * 4] = v;
    }
}

extern "C" void kernel_launch(void* const* d_in, const int* in_sizes, int n_in,
                              void* d_out, int out_size) {
    const float* Q    = (const float*)d_in[0];
    const float* K    = (const float*)d_in[1];
    const float* V    = (const float*)d_in[2];
    const int*   mask = (const int*)d_in[3];

    float* out  = (float*)d_out;                              // [B,H,S,D]
    float* attn = out + (size_t)NBH * SEQ * DIM;              // [B,H,S,S]

    dim3 g1(SEQ / 64, SEQ / 64, NBH);
    qk_kernel<<<g1, 256>>>(Q, K, attn);

    dim3 g2(SEQ, NBH);
    softmax_kernel<<<g2, 256>>>(attn, mask);

    dim3 g3(SEQ / 64, NBH);
    attnv_kernel<<<g3, 256>>>(attn, V, out);
}

// round 4
// speedup vs baseline: 11.8223x; 1.6572x over previous
#include <cuda_runtime.h>
#include <cuda_bf16.h>
#include <cstdint>

#define SEQ 2048
#define DIM 64
#define NBH 32   // B*H

// Transposed V scratch: [NBH][DIM][SEQ] bf16 hi/lo
__device__ __nv_bfloat16 g_vt_hi[(size_t)NBH * DIM * SEQ];
__device__ __nv_bfloat16 g_vt_lo[(size_t)NBH * DIM * SEQ];

// ---------------- helpers ----------------
__device__ __forceinline__ uint32_t smem_u32(const void* p) {
    uint32_t a;
    asm("{ .reg .u64 t; cvta.to.shared.u64 t, %1; cvt.u32.u64 %0, t; }" : "=r"(a) : "l"(p));
    return a;
}

__device__ __forceinline__ void ldsm_x4(uint32_t r[4], uint32_t addr) {
    asm volatile("ldmatrix.sync.aligned.m8n8.x4.shared.b16 {%0,%1,%2,%3}, [%4];"
        : "=r"(r[0]), "=r"(r[1]), "=r"(r[2]), "=r"(r[3]) : "r"(addr));
}
__device__ __forceinline__ void ldsm_x2(uint32_t r[2], uint32_t addr) {
    asm volatile("ldmatrix.sync.aligned.m8n8.x2.shared.b16 {%0,%1}, [%2];"
        : "=r"(r[0]), "=r"(r[1]) : "r"(addr));
}
__device__ __forceinline__ void mma16816(float c[4], const uint32_t a[4], const uint32_t b[2]) {
    asm volatile(
        "mma.sync.aligned.m16n8k16.row.col.f32.bf16.bf16.f32 "
        "{%0,%1,%2,%3}, {%4,%5,%6,%7}, {%8,%9}, {%0,%1,%2,%3};"
        : "+f"(c[0]), "+f"(c[1]), "+f"(c[2]), "+f"(c[3])
        : "r"(a[0]), "r"(a[1]), "r"(a[2]), "r"(a[3]), "r"(b[0]), "r"(b[1]));
}

__device__ __forceinline__ void split4(float4 v, uint32_t& h01, uint32_t& h23,
                                       uint32_t& l01, uint32_t& l23) {
    __nv_bfloat16 h0 = __float2bfloat16_rn(v.x);
    __nv_bfloat16 h1 = __float2bfloat16_rn(v.y);
    __nv_bfloat16 h2 = __float2bfloat16_rn(v.z);
    __nv_bfloat16 h3 = __float2bfloat16_rn(v.w);
    __nv_bfloat16 q0 = __float2bfloat16_rn(v.x - __bfloat162float(h0));
    __nv_bfloat16 q1 = __float2bfloat16_rn(v.y - __bfloat162float(h1));
    __nv_bfloat16 q2 = __float2bfloat16_rn(v.z - __bfloat162float(h2));
    __nv_bfloat16 q3 = __float2bfloat16_rn(v.w - __bfloat162float(h3));
    h01 = (uint32_t)__bfloat16_as_ushort(h0) | ((uint32_t)__bfloat16_as_ushort(h1) << 16);
    h23 = (uint32_t)__bfloat16_as_ushort(h2) | ((uint32_t)__bfloat16_as_ushort(h3) << 16);
    l01 = (uint32_t)__bfloat16_as_ushort(q0) | ((uint32_t)__bfloat16_as_ushort(q1) << 16);
    l23 = (uint32_t)__bfloat16_as_ushort(q2) | ((uint32_t)__bfloat16_as_ushort(q3) << 16);
}

// smem row stride: 72 bf16 = 144 bytes (conflict-free ldmatrix across 8 rows)
#define RS 72

// ---------------- Kernel 0: V -> Vt (bf16 hi/lo, [bh][n][k]) ----------------
__global__ __launch_bounds__(256) void vt_prep(const float* __restrict__ V) {
    __shared__ float tile[128][DIM + 1];
    const int bh = blockIdx.y;
    const int k0 = blockIdx.x * 128;
    const int tid = threadIdx.x;

    const float4* V4 = (const float4*)(V + ((size_t)bh * SEQ + k0) * DIM);
    #pragma unroll
    for (int p = 0; p < 8; p++) {
        int lin = tid + p * 256;
        int r = lin >> 4, j = lin & 15;
        float4 v = V4[lin];
        tile[r][j * 4 + 0] = v.x; tile[r][j * 4 + 1] = v.y;
        tile[r][j * 4 + 2] = v.z; tile[r][j * 4 + 3] = v.w;
    }
    __syncthreads();
    #pragma unroll
    for (int p = 0; p < 32; p++) {
        int lin = tid + p * 256;
        int n = lin >> 7, k = lin & 127;
        float x = tile[k][n];
        __nv_bfloat16 h = __float2bfloat16_rn(x);
        __nv_bfloat16 l = __float2bfloat16_rn(x - __bfloat162float(h));
        size_t o = ((size_t)bh * DIM + n) * SEQ + k0 + k;
        g_vt_hi[o] = h;
        g_vt_lo[o] = l;
    }
}

// ---------------- Kernel 1: scores = QK^T * 0.125 (HMMA) --------------------
// Block: 128x128 tile, 256 threads (8 warps as 2m x 4n).
__global__ __launch_bounds__(256) void qk_mma(const float* __restrict__ Q,
                                              const float* __restrict__ K,
                                              float* __restrict__ scores) {
    extern __shared__ char sm[];
    constexpr int QHI = 0, QLO = 18432, KHI = 36864, KLO = 55296;
    const uint32_t sb = smem_u32(sm);
    const int tid = threadIdx.x, wid = tid >> 5, l = tid & 31;
    const int bh = blockIdx.z, m0 = blockIdx.y * 128, n0 = blockIdx.x * 128;

    const float4* Qg = (const float4*)(Q + ((size_t)bh * SEQ + m0) * DIM);
    const float4* Kg = (const float4*)(K + ((size_t)bh * SEQ + n0) * DIM);
    #pragma unroll
    for (int p = 0; p < 8; p++) {
        int lin = tid + p * 256;
        int r = lin >> 4, j = lin & 15;
        uint32_t off = (uint32_t)(r * RS + j * 4) * 2;
        uint32_t h01, h23, l01, l23;
        split4(Qg[lin], h01, h23, l01, l23);
        *(uint2*)(sm + QHI + off) = make_uint2(h01, h23);
        *(uint2*)(sm + QLO + off) = make_uint2(l01, l23);
        split4(Kg[lin], h01, h23, l01, l23);
        *(uint2*)(sm + KHI + off) = make_uint2(h01, h23);
        *(uint2*)(sm + KLO + off) = make_uint2(l01, l23);
    }
    __syncthreads();

    const int wm = wid >> 2, wn = wid & 3;
    const int mbase = wm * 64, nbase = wn * 32;
    const int lr = l & 7, sub = l >> 3;

    float acc[4][4][4];
    #pragma unroll
    for (int a = 0; a < 4; a++)
        #pragma unroll
        for (int b = 0; b < 4; b++)
            #pragma unroll
            for (int c = 0; c < 4; c++) acc[a][b][c] = 0.f;

    // lane-fixed parts of ldmatrix addresses
    const int arow_lane = lr + (sub & 1) * 8;     // + mbase + mt*16
    const uint32_t akc_lane = (uint32_t)((sub >> 1) * 8);  // + ks*16
    const int brow_lane = lr;                     // + nbase + nt*8
    const uint32_t bkc_lane = (uint32_t)((sub & 1) * 8);   // + ks*16

    #pragma unroll
    for (int ks = 0; ks < 4; ks++) {
        uint32_t ah[4][4], al[4][4];
        #pragma unroll
        for (int mt = 0; mt < 4; mt++) {
            int row = mbase + mt * 16 + arow_lane;
            uint32_t off = (uint32_t)(row * RS) * 2 + (akc_lane + ks * 16) * 2;
            ldsm_x4(ah[mt], sb + QHI + off);
            ldsm_x4(al[mt], sb + QLO + off);
        }
        #pragma unroll
        for (int nt = 0; nt < 4; nt++) {
            int rowN = nbase + nt * 8 + brow_lane;
            uint32_t off = (uint32_t)(rowN * RS) * 2 + (bkc_lane + ks * 16) * 2;
            uint32_t bhf[2], blf[2];
            ldsm_x2(bhf, sb + KHI + off);
            ldsm_x2(blf, sb + KLO + off);
            #pragma unroll
            for (int mt = 0; mt < 4; mt++) {
                mma16816(acc[mt][nt], ah[mt], bhf);
                mma16816(acc[mt][nt], ah[mt], blf);
                mma16816(acc[mt][nt], al[mt], bhf);
            }
        }
    }

    const int g = l >> 2, q2 = (l & 3) * 2;
    float* so = scores + (size_t)bh * SEQ * SEQ;
    #pragma unroll
    for (int mt = 0; mt < 4; mt++) {
        #pragma unroll
        for (int nt = 0; nt < 4; nt++) {
            int row = m0 + mbase + mt * 16 + g;
            int col = n0 + nbase + nt * 8 + q2;
            *(float2*)&so[(size_t)row * SEQ + col] =
                make_float2(acc[mt][nt][0] * 0.125f, acc[mt][nt][1] * 0.125f);
            *(float2*)&so[(size_t)(row + 8) * SEQ + col] =
                make_float2(acc[mt][nt][2] * 0.125f, acc[mt][nt][3] * 0.125f);
        }
    }
}

// ---------------- Kernel 2: masked softmax (in-place rows) ------------------
__inline__ __device__ float warpMax(float v) {
    #pragma unroll
    for (int o = 16; o > 0; o >>= 1) v = fmaxf(v, __shfl_xor_sync(0xffffffffu, v, o));
    return v;
}
__inline__ __device__ float warpSum(float v) {
    #pragma unroll
    for (int o = 16; o > 0; o >>= 1) v += __shfl_xor_sync(0xffffffffu, v, o);
    return v;
}
__global__ __launch_bounds__(256) void softmax_kernel(float* __restrict__ attn,
                                                      const int* __restrict__ mask) {
    const int q = blockIdx.x, bh = blockIdx.y, tid = threadIdx.x;
    float4* row = (float4*)(attn + ((size_t)bh * SEQ + q) * SEQ);
    const int4* mrow = (const int4*)(mask + (size_t)q * SEQ);
    __shared__ float red[8];

    float4 v0 = row[tid], v1 = row[tid + 256];
    int4 k0 = mrow[tid], k1 = mrow[tid + 256];
    v0.x = (k0.x == 0) ? -1.0e9f : v0.x;  v0.y = (k0.y == 0) ? -1.0e9f : v0.y;
    v0.z = (k0.z == 0) ? -1.0e9f : v0.z;  v0.w = (k0.w == 0) ? -1.0e9f : v0.w;
    v1.x = (k1.x == 0) ? -1.0e9f : v1.x;  v1.y = (k1.y == 0) ? -1.0e9f : v1.y;
    v1.z = (k1.z == 0) ? -1.0e9f : v1.z;  v1.w = (k1.w == 0) ? -1.0e9f : v1.w;

    float m = fmaxf(fmaxf(fmaxf(v0.x, v0.y), fmaxf(v0.z, v0.w)),
                    fmaxf(fmaxf(v1.x, v1.y), fmaxf(v1.z, v1.w)));
    m = warpMax(m);
    if ((tid & 31) == 0) red[tid >> 5] = m;
    __syncthreads();
    if (tid < 32) { float t = (tid < 8) ? red[tid] : -3.0e38f; t = warpMax(t); if (tid == 0) red[0] = t; }
    __syncthreads();
    m = red[0];
    __syncthreads();

    v0.x = __expf(v0.x - m); v0.y = __expf(v0.y - m); v0.z = __expf(v0.z - m); v0.w = __expf(v0.w - m);
    v1.x = __expf(v1.x - m); v1.y = __expf(v1.y - m); v1.z = __expf(v1.z - m); v1.w = __expf(v1.w - m);
    float s = (v0.x + v0.y) + (v0.z + v0.w) + (v1.x + v1.y) + (v1.z + v1.w);
    s = warpSum(s);
    if ((tid & 31) == 0) red[tid >> 5] = s;
    __syncthreads();
    if (tid < 32) { float t = (tid < 8) ? red[tid] : 0.f; t = warpSum(t); if (tid == 0) red[0] = t; }
    __syncthreads();
    const float inv = 1.0f / red[0];
    v0.x *= inv; v0.y *= inv; v0.z *= inv; v0.w *= inv;
    v1.x *= inv; v1.y *= inv; v1.z *= inv; v1.w *= inv;
    row[tid] = v0; row[tid + 256] = v1;
}

// ---------------- Kernel 3: out = attn @ V (HMMA, K-loop) -------------------
// Block: 128(m) x 64(n), K chunks of 64. 8 warps as 4m x 2n.
__global__ __launch_bounds__(256) void attnv_mma(const float* __restrict__ attn,
                                                 float* __restrict__ out) {
    extern __shared__ char sm[];
    constexpr int AHI = 0, ALO = 18432, BHI = 36864, BLO = 46080;
    const uint32_t sb = smem_u32(sm);
    const int tid = threadIdx.x, wid = tid >> 5, l = tid & 31;
    const int bh = blockIdx.y, m0 = blockIdx.x * 128;

    const int wm = wid >> 1, wn = wid & 1;
    const int mbase = wm * 32, nbase = wn * 32;
    const int lr = l & 7, sub = l >> 3;
    const int arow_lane = lr + (sub & 1) * 8;
    const uint32_t akc_lane = (uint32_t)((sub >> 1) * 8);
    const uint32_t bkc_lane = (uint32_t)((sub & 1) * 8);

    const float4* Ag = (const float4*)(attn + ((size_t)bh * SEQ + m0) * SEQ);
    const __nv_bfloat16* vh = g_vt_hi + (size_t)bh * DIM * SEQ;
    const __nv_bfloat16* vl = g_vt_lo + (size_t)bh * DIM * SEQ;

    float acc[2][4][4];
    #pragma unroll
    for (int a = 0; a < 2; a++)
        #pragma unroll
        for (int b = 0; b < 4; b++)
            #pragma unroll
            for (int c = 0; c < 4; c++) acc[a][b][c] = 0.f;

    for (int kt = 0; kt < SEQ / 64; kt++) {
        // A chunk: attn[m0..+127][kt*64..+63] -> bf16 hi/lo
        #pragma unroll
        for (int p = 0; p < 8; p++) {
            int lin = tid + p * 256;
            int r = lin >> 4, j = lin & 15;
            float4 v = Ag[(size_t)r * (SEQ / 4) + kt * 16 + j];
            uint32_t h01, h23, l01, l23;
            split4(v, h01, h23, l01, l23);
            uint32_t off = (uint32_t)(r * RS + j * 4) * 2;
            *(uint2*)(sm + AHI + off) = make_uint2(h01, h23);
            *(uint2*)(sm + ALO + off) = make_uint2(l01, l23);
        }
        // B chunk: Vt[0..63][kt*64..+63] bf16 (pre-split)
        #pragma unroll
        for (int p = 0; p < 2; p++) {
            int lin = tid + p * 256;
            int n = lin >> 3, jj = lin & 7;
            size_t go = (size_t)n * SEQ + kt * 64 + jj * 8;
            uint32_t off = (uint32_t)(n * RS + jj * 8) * 2;
            *(uint4*)(sm + BHI + off) = *(const uint4*)(vh + go);
            *(uint4*)(sm + BLO + off) = *(const uint4*)(vl + go);
        }
        __syncthreads();

        #pragma unroll
        for (int ks = 0; ks < 4; ks++) {
            uint32_t ah[2][4], al[2][4];
            #pragma unroll
            for (int mt = 0; mt < 2; mt++) {
                int row = mbase + mt * 16 + arow_lane;
                uint32_t off = (uint32_t)(row * RS) * 2 + (akc_lane + ks * 16) * 2;
                ldsm_x4(ah[mt], sb + AHI + off);
                ldsm_x4(al[mt], sb + ALO + off);
            }
            #pragma unroll
            for (int nt = 0; nt < 4; nt++) {
                int rowN = nbase + nt * 8 + lr;
                uint32_t off = (uint32_t)(rowN * RS) * 2 + (bkc_lane + ks * 16) * 2;
                uint32_t bhf[2], blf[2];
                ldsm_x2(bhf, sb + BHI + off);
                ldsm_x2(blf, sb + BLO + off);
                #pragma unroll
                for (int mt = 0; mt < 2; mt++) {
                    mma16816(acc[mt][nt], ah[mt], bhf);
                    mma16816(acc[mt][nt], ah[mt], blf);
                    mma16816(acc[mt][nt], al[mt], bhf);
                }
            }
        }
        __syncthreads();
    }

    const int g = l >> 2, q2 = (l & 3) * 2;
    float* ob = out + ((size_t)bh * SEQ + m0) * DIM;
    #pragma unroll
    for (int mt = 0; mt < 2; mt++) {
        #pragma unroll
        for (int nt = 0; nt < 4; nt++) {
            int row = mbase + mt * 16 + g;
            int col = nbase + nt * 8 + q2;
            *(float2*)&ob[(size_t)row * DIM + col] = make_float2(acc[mt][nt][0], acc[mt][nt][1]);
            *(float2*)&ob[(size_t)(row + 8) * DIM + col] = make_float2(acc[mt][nt][2], acc[mt][nt][3]);
        }
    }
}

// ---------------- launch ----------------
extern "C" void kernel_launch(void* const* d_in, const int* in_sizes, int n_in,
                              void* d_out, int out_size) {
    const float* Q    = (const float*)d_in[0];
    const float* K    = (const float*)d_in[1];
    const float* V    = (const float*)d_in[2];
    const int*   mask = (const int*)d_in[3];

    float* out  = (float*)d_out;                      // [B,H,S,D]
    float* attn = out + (size_t)NBH * SEQ * DIM;      // [B,H,S,S]

    constexpr int QK_SMEM = 4 * 128 * RS * 2;         // 73728
    constexpr int AV_SMEM = 2 * 128 * RS * 2 + 2 * 64 * RS * 2;  // 55296
    cudaFuncSetAttribute(qk_mma, cudaFuncAttributeMaxDynamicSharedMemorySize, QK_SMEM);
    cudaFuncSetAttribute(attnv_mma, cudaFuncAttributeMaxDynamicSharedMemorySize, AV_SMEM);

    dim3 g0(SEQ / 128, NBH);
    vt_prep<<<g0, 256>>>(V);

    dim3 g1(SEQ / 128, SEQ / 128, NBH);
    qk_mma<<<g1, 256, QK_SMEM>>>(Q, K, attn);

    dim3 g2(SEQ, NBH);
    softmax_kernel<<<g2, 256>>>(attn, mask);

    dim3 g3(SEQ / 128, NBH);
    attnv_mma<<<g3, 256, AV_SMEM>>>(attn, out);
}